// round 4
// baseline (speedup 1.0000x reference)
#include <cuda_runtime.h>

// ChamferLoss: B=8, N=M=8192, D=3 fp32.
// out = mean_n min_m ||gt_n - pred_m||^2  +  mean_m min_n ||pred_m - gt_n||^2
//
// Compute-bound on the FP32 pipe. Uses the a2+b2-2ab trick (matches the
// reference numerics) with packed fma.rn.f32x2 (Blackwell f32x2 datapath,
// 2 pairs per FFMA) and register blocking of 8 A-points per thread so the
// shared-memory B reads amortize to ~nothing.

#define BATCH   8
#define NPTS    8192
#define THREADS 256
#define TA      8                       // A points per thread
#define ATILE   (THREADS * TA)          // 2048 A points per block
#define NATILE  (NPTS / ATILE)          // 4
#define BCHUNK  1024                    // B points per block
#define NCHUNK  (NPTS / BCHUNK)         // 8
#define NRBLK   (NPTS / THREADS)        // 32 combine blocks per (b,dir)

// Scratch: per-(dir,batch,chunk) partial mins for every A point. 4 MB.
__device__ float g_partial[2 * BATCH * NCHUNK * NPTS];
// Per-combine-block partial sums: 2*8*32 = 512 floats.
__device__ float g_blocksums[2 * BATCH * NRBLK];

__device__ __forceinline__ unsigned long long pack2(float lo, float hi) {
    unsigned long long r;
    asm("mov.b64 %0, {%1, %2};" : "=l"(r) : "f"(lo), "f"(hi));
    return r;
}
__device__ __forceinline__ void unpack2(unsigned long long v, float& lo, float& hi) {
    asm("mov.b64 {%0, %1}, %2;" : "=f"(lo), "=f"(hi) : "l"(v));
}
__device__ __forceinline__ unsigned long long fma2(unsigned long long a,
                                                   unsigned long long b,
                                                   unsigned long long c) {
    unsigned long long d;
    asm("fma.rn.f32x2 %0, %1, %2, %3;" : "=l"(d) : "l"(a), "l"(b), "l"(c));
    return d;
}

// ---------------------------------------------------------------------------
// Main kernel: for each A point, min over a BCHUNK slice of B points of
//   t = b2 - 2*(ax*bx + ay*by + az*bz)        (min d2 = a2 + min t, clamped later)
// grid: (NATILE*NCHUNK, BATCH, 2)   block: 256 threads
// ---------------------------------------------------------------------------
__global__ __launch_bounds__(THREADS)
void chamfer_main(const float* __restrict__ gts, const float* __restrict__ preds) {
    const int dir   = blockIdx.z;                 // 0: A=gts,B=preds ; 1: swapped
    const int b     = blockIdx.y;
    const int tileA = blockIdx.x >> 3;            // / NCHUNK
    const int chunk = blockIdx.x & (NCHUNK - 1);

    const float* Ab = (dir == 0 ? gts : preds) + (size_t)b * NPTS * 3;
    const float* Bb = (dir == 0 ? preds : gts) + (size_t)b * NPTS * 3
                      + (size_t)chunk * BCHUNK * 3;

    // B chunk staged once, pre-duplicated into packed f32x2 lanes:
    //   smu[2j]   = { {bx,bx}, {by,by} }
    //   smu[2j+1] = { {bz,bz}, {b2,b2} }
    // LDS.128 of ulonglong2 lands the duplicated pairs directly in aligned
    // register pairs — zero pack MOVs in the hot loop.
    __shared__ ulonglong2 smu[2 * BCHUNK];        // 32 KB

    const int tid = threadIdx.x;
    for (int i = tid; i < BCHUNK; i += THREADS) {
        float bx = Bb[3 * i + 0];
        float by = Bb[3 * i + 1];
        float bz = Bb[3 * i + 2];
        float b2 = bx * bx + by * by + bz * bz;
        ulonglong2 v0; v0.x = pack2(bx, bx); v0.y = pack2(by, by);
        ulonglong2 v1; v1.x = pack2(bz, bz); v1.y = pack2(b2, b2);
        smu[2 * i + 0] = v0;
        smu[2 * i + 1] = v1;
    }

    // Register-blocked A coefficients, scaled by -2, packed in f32x2 pairs.
    // Thread owns local A indices la = tid + k*THREADS, k in [0,8).
    unsigned long long axm[TA / 2], aym[TA / 2], azm[TA / 2];
#pragma unroll
    for (int g = 0; g < TA / 2; ++g) {
        int i0 = tileA * ATILE + tid + (2 * g) * THREADS;
        int i1 = i0 + THREADS;
        float ax0 = Ab[3 * i0 + 0], ay0 = Ab[3 * i0 + 1], az0 = Ab[3 * i0 + 2];
        float ax1 = Ab[3 * i1 + 0], ay1 = Ab[3 * i1 + 1], az1 = Ab[3 * i1 + 2];
        axm[g] = pack2(-2.0f * ax0, -2.0f * ax1);
        aym[g] = pack2(-2.0f * ay0, -2.0f * ay1);
        azm[g] = pack2(-2.0f * az0, -2.0f * az1);
    }

    float m[TA];
#pragma unroll
    for (int k = 0; k < TA; ++k) m[k] = 3.402823466e+38f;

    __syncthreads();

    // Hot loop: per j per thread -> 2 LDS.128 (broadcast) + 12 FFMA2 + 8 FMNMX
    // covering 8 pairs. fma-pipe bound ~10.6 pairs/cyc/SMSP.
#pragma unroll 4
    for (int j = 0; j < BCHUNK; ++j) {
        ulonglong2 u0 = smu[2 * j + 0];
        ulonglong2 u1 = smu[2 * j + 1];
#pragma unroll
        for (int g = 0; g < TA / 2; ++g) {
            unsigned long long t = fma2(axm[g], u0.x, u1.y);   // b2 - 2ax*bx
            t = fma2(aym[g], u0.y, t);
            t = fma2(azm[g], u1.x, t);
            float lo, hi;
            unpack2(t, lo, hi);
            m[2 * g + 0] = fminf(m[2 * g + 0], lo);
            m[2 * g + 1] = fminf(m[2 * g + 1], hi);
        }
    }

    const int slot = (dir * BATCH + b) * NCHUNK + chunk;
    float* pp = g_partial + (size_t)slot * NPTS + tileA * ATILE;
#pragma unroll
    for (int k = 0; k < TA; ++k)
        pp[tid + k * THREADS] = m[k];
}

// ---------------------------------------------------------------------------
// Combine: min over chunks, add a2, clamp at 0, deterministic block-tree sum.
// grid: (NRBLK, BATCH, 2)   block: 256 threads
// ---------------------------------------------------------------------------
__global__ __launch_bounds__(THREADS)
void chamfer_combine(const float* __restrict__ gts, const float* __restrict__ preds) {
    const int dir  = blockIdx.z;
    const int b    = blockIdx.y;
    const int aidx = blockIdx.x * THREADS + threadIdx.x;
    const float* Ab = (dir == 0 ? gts : preds) + (size_t)b * NPTS * 3;

    const int slotbase = (dir * BATCH + b) * NCHUNK;
    float mmin = 3.402823466e+38f;
#pragma unroll
    for (int c = 0; c < NCHUNK; ++c)
        mmin = fminf(mmin, g_partial[(size_t)(slotbase + c) * NPTS + aidx]);

    float ax = Ab[3 * aidx + 0];
    float ay = Ab[3 * aidx + 1];
    float az = Ab[3 * aidx + 2];
    float a2 = ax * ax + ay * ay + az * az;
    float v  = fmaxf(a2 + mmin, 0.0f);   // clamp commutes with min (monotone)

    __shared__ float red[THREADS];
    red[threadIdx.x] = v;
    __syncthreads();
#pragma unroll
    for (int s = THREADS / 2; s > 0; s >>= 1) {
        if (threadIdx.x < s) red[threadIdx.x] += red[threadIdx.x + s];
        __syncthreads();
    }
    if (threadIdx.x == 0)
        g_blocksums[(dir * BATCH + b) * NRBLK + blockIdx.x] = red[0];
}

// ---------------------------------------------------------------------------
// Final: sum the 512 block sums, divide by BATCH*NPTS (both means share the
// denominator since N == M). One block of 512 threads.
// ---------------------------------------------------------------------------
__global__ void chamfer_final(float* __restrict__ out) {
    __shared__ float red[512];
    red[threadIdx.x] = g_blocksums[threadIdx.x];
    __syncthreads();
#pragma unroll
    for (int s = 256; s > 0; s >>= 1) {
        if (threadIdx.x < s) red[threadIdx.x] += red[threadIdx.x + s];
        __syncthreads();
    }
    if (threadIdx.x == 0)
        out[0] = red[0] / (float)(BATCH * NPTS);
}

extern "C" void kernel_launch(void* const* d_in, const int* in_sizes, int n_in,
                              void* d_out, int out_size) {
    const float* gts   = (const float*)d_in[0];
    const float* preds = (const float*)d_in[1];
    (void)in_sizes; (void)n_in; (void)out_size;

    dim3 g1(NATILE * NCHUNK, BATCH, 2);     // 32 x 8 x 2 = 512 blocks
    chamfer_main<<<g1, THREADS>>>(gts, preds);

    dim3 g2(NRBLK, BATCH, 2);               // 32 x 8 x 2 = 512 blocks
    chamfer_combine<<<g2, THREADS>>>(gts, preds);

    chamfer_final<<<1, 512>>>((float*)d_out);
}

// round 6
// speedup vs baseline: 1.1521x; 1.1521x over previous
#include <cuda_runtime.h>

// ChamferLoss: B=8, N=M=8192, D=3 fp32.
// out = mean_n min_m ||gt_n - pred_m||^2  +  mean_m min_n ||pred_m - gt_n||^2
//
// FP32-pipe-bound. a2+b2-2ab trick (matches reference numerics) with packed
// fma.rn.f32x2 (Blackwell FFMA2), scalar fminf for the running min (no packed
// f32x2 min exists in PTX), 8 A-points register-blocked per thread, B chunk
// staged pre-duplicated in shared so LDS.128 broadcast feeds packed register
// pairs directly.
//
// R5 vs R3 (195us, fma=42% alu=35% issue=53% occ=35%):
//  - BCHUNK 1024->512: smem 33->16KB, grid 512->1024 blocks -> 5 blocks/SM
//    (reg-limited at 48 regs) = 62% occupancy, to lift issue efficiency
//    toward the ~93us fma-pipe floor.

#define BATCH   8
#define NPTS    8192
#define THREADS 256
#define TA      8                       // A points per thread
#define ATILE   (THREADS * TA)          // 2048 A points per block
#define NATILE  (NPTS / ATILE)          // 4
#define BCHUNK  512                     // B points per block
#define NCHUNK  (NPTS / BCHUNK)         // 16
#define NRBLK   (NPTS / THREADS)        // 32 combine blocks per (b,dir)

// Scratch: per-(dir,batch,chunk) partial mins for every A point. 8 MB.
__device__ float g_partial[2 * BATCH * NCHUNK * NPTS];
// Per-combine-block partial sums: 2*8*32 = 512 floats.
__device__ float g_blocksums[2 * BATCH * NRBLK];

__device__ __forceinline__ unsigned long long pack2(float lo, float hi) {
    unsigned long long r;
    asm("mov.b64 %0, {%1, %2};" : "=l"(r) : "f"(lo), "f"(hi));
    return r;
}
__device__ __forceinline__ void unpack2(unsigned long long v, float& lo, float& hi) {
    asm("mov.b64 {%0, %1}, %2;" : "=f"(lo), "=f"(hi) : "l"(v));
}
__device__ __forceinline__ unsigned long long fma2(unsigned long long a,
                                                   unsigned long long b,
                                                   unsigned long long c) {
    unsigned long long d;
    asm("fma.rn.f32x2 %0, %1, %2, %3;" : "=l"(d) : "l"(a), "l"(b), "l"(c));
    return d;
}

// ---------------------------------------------------------------------------
// Main kernel: for each A point, min over a BCHUNK slice of B points of
//   t = b2 - 2*(ax*bx + ay*by + az*bz)        (min d2 = a2 + min t, clamp later)
// grid: (NATILE*NCHUNK, BATCH, 2)   block: 256 threads
// ---------------------------------------------------------------------------
__global__ __launch_bounds__(THREADS)
void chamfer_main(const float* __restrict__ gts, const float* __restrict__ preds) {
    const int dir   = blockIdx.z;                 // 0: A=gts,B=preds ; 1: swapped
    const int b     = blockIdx.y;
    const int tileA = blockIdx.x >> 4;            // / NCHUNK
    const int chunk = blockIdx.x & (NCHUNK - 1);

    const float* Ab = (dir == 0 ? gts : preds) + (size_t)b * NPTS * 3;
    const float* Bb = (dir == 0 ? preds : gts) + (size_t)b * NPTS * 3
                      + (size_t)chunk * BCHUNK * 3;

    // B chunk staged once, pre-duplicated into packed f32x2 lanes:
    //   smu[2j]   = { {bx,bx}, {by,by} }
    //   smu[2j+1] = { {bz,bz}, {b2,b2} }
    // LDS.128 broadcast lands duplicated pairs directly in aligned reg pairs.
    __shared__ ulonglong2 smu[2 * BCHUNK];        // 16 KB

    const int tid = threadIdx.x;
    for (int i = tid; i < BCHUNK; i += THREADS) {
        float bx = Bb[3 * i + 0];
        float by = Bb[3 * i + 1];
        float bz = Bb[3 * i + 2];
        float b2 = bx * bx + by * by + bz * bz;
        ulonglong2 v0; v0.x = pack2(bx, bx); v0.y = pack2(by, by);
        ulonglong2 v1; v1.x = pack2(bz, bz); v1.y = pack2(b2, b2);
        smu[2 * i + 0] = v0;
        smu[2 * i + 1] = v1;
    }

    // Register-blocked A coefficients, scaled by -2, packed in f32x2 pairs.
    unsigned long long axm[TA / 2], aym[TA / 2], azm[TA / 2];
#pragma unroll
    for (int g = 0; g < TA / 2; ++g) {
        int i0 = tileA * ATILE + tid + (2 * g) * THREADS;
        int i1 = i0 + THREADS;
        float ax0 = Ab[3 * i0 + 0], ay0 = Ab[3 * i0 + 1], az0 = Ab[3 * i0 + 2];
        float ax1 = Ab[3 * i1 + 0], ay1 = Ab[3 * i1 + 1], az1 = Ab[3 * i1 + 2];
        axm[g] = pack2(-2.0f * ax0, -2.0f * ax1);
        aym[g] = pack2(-2.0f * ay0, -2.0f * ay1);
        azm[g] = pack2(-2.0f * az0, -2.0f * az1);
    }

    float m[TA];
#pragma unroll
    for (int k = 0; k < TA; ++k) m[k] = 3.402823466e+38f;

    __syncthreads();

    // Hot loop per j per thread: 2 LDS.128 (broadcast) + 12 FFMA2 (fma pipe,
    // 24 cyc binding) + 8 FMNMX (alu pipe, parallel) covering 8 pairs.
    // unpack2 is register aliasing only (no SASS op).
#pragma unroll 8
    for (int j = 0; j < BCHUNK; ++j) {
        ulonglong2 u0 = smu[2 * j + 0];
        ulonglong2 u1 = smu[2 * j + 1];
#pragma unroll
        for (int g = 0; g < TA / 2; ++g) {
            unsigned long long t = fma2(axm[g], u0.x, u1.y);   // b2 - 2ax*bx
            t = fma2(aym[g], u0.y, t);
            t = fma2(azm[g], u1.x, t);
            float lo, hi;
            unpack2(t, lo, hi);
            m[2 * g + 0] = fminf(m[2 * g + 0], lo);
            m[2 * g + 1] = fminf(m[2 * g + 1], hi);
        }
    }

    const int slot = (dir * BATCH + b) * NCHUNK + chunk;
    float* pp = g_partial + (size_t)slot * NPTS + tileA * ATILE;
#pragma unroll
    for (int k = 0; k < TA; ++k)
        pp[tid + k * THREADS] = m[k];
}

// ---------------------------------------------------------------------------
// Combine: min over chunks, add a2, clamp at 0, deterministic block-tree sum.
// grid: (NRBLK, BATCH, 2)   block: 256 threads
// ---------------------------------------------------------------------------
__global__ __launch_bounds__(THREADS)
void chamfer_combine(const float* __restrict__ gts, const float* __restrict__ preds) {
    const int dir  = blockIdx.z;
    const int b    = blockIdx.y;
    const int aidx = blockIdx.x * THREADS + threadIdx.x;
    const float* Ab = (dir == 0 ? gts : preds) + (size_t)b * NPTS * 3;

    const int slotbase = (dir * BATCH + b) * NCHUNK;
    float mmin = 3.402823466e+38f;
#pragma unroll
    for (int c = 0; c < NCHUNK; ++c)
        mmin = fminf(mmin, g_partial[(size_t)(slotbase + c) * NPTS + aidx]);

    float ax = Ab[3 * aidx + 0];
    float ay = Ab[3 * aidx + 1];
    float az = Ab[3 * aidx + 2];
    float a2 = ax * ax + ay * ay + az * az;
    float v  = fmaxf(a2 + mmin, 0.0f);   // clamp commutes with min (monotone)

    __shared__ float red[THREADS];
    red[threadIdx.x] = v;
    __syncthreads();
#pragma unroll
    for (int s = THREADS / 2; s > 0; s >>= 1) {
        if (threadIdx.x < s) red[threadIdx.x] += red[threadIdx.x + s];
        __syncthreads();
    }
    if (threadIdx.x == 0)
        g_blocksums[(dir * BATCH + b) * NRBLK + blockIdx.x] = red[0];
}

// ---------------------------------------------------------------------------
// Final: sum the 512 block sums, divide by BATCH*NPTS (both means share the
// denominator since N == M). One block of 512 threads.
// ---------------------------------------------------------------------------
__global__ void chamfer_final(float* __restrict__ out) {
    __shared__ float red[512];
    red[threadIdx.x] = g_blocksums[threadIdx.x];
    __syncthreads();
#pragma unroll
    for (int s = 256; s > 0; s >>= 1) {
        if (threadIdx.x < s) red[threadIdx.x] += red[threadIdx.x + s];
        __syncthreads();
    }
    if (threadIdx.x == 0)
        out[0] = red[0] / (float)(BATCH * NPTS);
}

extern "C" void kernel_launch(void* const* d_in, const int* in_sizes, int n_in,
                              void* d_out, int out_size) {
    const float* gts   = (const float*)d_in[0];
    const float* preds = (const float*)d_in[1];
    (void)in_sizes; (void)n_in; (void)out_size;

    dim3 g1(NATILE * NCHUNK, BATCH, 2);     // 64 x 8 x 2 = 1024 blocks
    chamfer_main<<<g1, THREADS>>>(gts, preds);

    dim3 g2(NRBLK, BATCH, 2);               // 32 x 8 x 2 = 512 blocks
    chamfer_combine<<<g2, THREADS>>>(gts, preds);

    chamfer_final<<<1, 512>>>((float*)d_out);
}

// round 7
// speedup vs baseline: 1.2147x; 1.0543x over previous
#include <cuda_runtime.h>

// ChamferLoss: B=8, N=M=8192, D=3 fp32.
// out = mean_n min_m ||gt_n - pred_m||^2  +  mean_m min_n ||pred_m - gt_n||^2
//
// FP32-pipe-bound. a2+b2-2ab trick (matches reference numerics) with packed
// fma.rn.f32x2 (Blackwell FFMA2), scalar fminf running min, 8 A-points
// register-blocked per thread, B chunk staged pre-duplicated in shared.
//
// R6 change vs R5 (169.5us, fma=49% issue=49% occ=40%): explicit distance-1
// software pipeline of the 2 LDS.128 per iteration (register double-buffer).
// R5's coherent whole-SMSP stall came from same-iteration LDS->FFMA2
// dependency (29-cyc LDS latency exposed to all lockstep warps at once).

#define BATCH   8
#define NPTS    8192
#define THREADS 256
#define TA      8                       // A points per thread
#define ATILE   (THREADS * TA)          // 2048 A points per block
#define NATILE  (NPTS / ATILE)          // 4
#define BCHUNK  512                     // B points per block
#define NCHUNK  (NPTS / BCHUNK)         // 16
#define NRBLK   (NPTS / THREADS)        // 32 combine blocks per (b,dir)

// Scratch: per-(dir,batch,chunk) partial mins for every A point. 8 MB.
__device__ float g_partial[2 * BATCH * NCHUNK * NPTS];
// Per-combine-block partial sums: 2*8*32 = 512 floats.
__device__ float g_blocksums[2 * BATCH * NRBLK];

__device__ __forceinline__ unsigned long long pack2(float lo, float hi) {
    unsigned long long r;
    asm("mov.b64 %0, {%1, %2};" : "=l"(r) : "f"(lo), "f"(hi));
    return r;
}
__device__ __forceinline__ void unpack2(unsigned long long v, float& lo, float& hi) {
    asm("mov.b64 {%0, %1}, %2;" : "=f"(lo), "=f"(hi) : "l"(v));
}
__device__ __forceinline__ unsigned long long fma2(unsigned long long a,
                                                   unsigned long long b,
                                                   unsigned long long c) {
    unsigned long long d;
    asm("fma.rn.f32x2 %0, %1, %2, %3;" : "=l"(d) : "l"(a), "l"(b), "l"(c));
    return d;
}

// ---------------------------------------------------------------------------
// Main kernel: for each A point, min over a BCHUNK slice of B points of
//   t = b2 - 2*(ax*bx + ay*by + az*bz)        (min d2 = a2 + min t, clamp later)
// grid: (NATILE*NCHUNK, BATCH, 2)   block: 256 threads
// ---------------------------------------------------------------------------
__global__ __launch_bounds__(THREADS, 4)
void chamfer_main(const float* __restrict__ gts, const float* __restrict__ preds) {
    const int dir   = blockIdx.z;                 // 0: A=gts,B=preds ; 1: swapped
    const int b     = blockIdx.y;
    const int tileA = blockIdx.x >> 4;            // / NCHUNK
    const int chunk = blockIdx.x & (NCHUNK - 1);

    const float* Ab = (dir == 0 ? gts : preds) + (size_t)b * NPTS * 3;
    const float* Bb = (dir == 0 ? preds : gts) + (size_t)b * NPTS * 3
                      + (size_t)chunk * BCHUNK * 3;

    // B chunk staged once, pre-duplicated into packed f32x2 lanes:
    //   smu[2j]   = { {bx,bx}, {by,by} }
    //   smu[2j+1] = { {bz,bz}, {b2,b2} }
    // +2 pad entries so the distance-1 prefetch can read unconditionally.
    __shared__ ulonglong2 smu[2 * BCHUNK + 2];    // ~16 KB

    const int tid = threadIdx.x;
    for (int i = tid; i < BCHUNK; i += THREADS) {
        float bx = Bb[3 * i + 0];
        float by = Bb[3 * i + 1];
        float bz = Bb[3 * i + 2];
        float b2 = bx * bx + by * by + bz * bz;
        ulonglong2 v0; v0.x = pack2(bx, bx); v0.y = pack2(by, by);
        ulonglong2 v1; v1.x = pack2(bz, bz); v1.y = pack2(b2, b2);
        smu[2 * i + 0] = v0;
        smu[2 * i + 1] = v1;
    }
    if (tid == 0) {
        smu[2 * BCHUNK + 0] = smu[0];   // harmless pad values
        smu[2 * BCHUNK + 1] = smu[1];
    }

    // Register-blocked A coefficients, scaled by -2, packed in f32x2 pairs.
    unsigned long long axm[TA / 2], aym[TA / 2], azm[TA / 2];
#pragma unroll
    for (int g = 0; g < TA / 2; ++g) {
        int i0 = tileA * ATILE + tid + (2 * g) * THREADS;
        int i1 = i0 + THREADS;
        float ax0 = Ab[3 * i0 + 0], ay0 = Ab[3 * i0 + 1], az0 = Ab[3 * i0 + 2];
        float ax1 = Ab[3 * i1 + 0], ay1 = Ab[3 * i1 + 1], az1 = Ab[3 * i1 + 2];
        axm[g] = pack2(-2.0f * ax0, -2.0f * ax1);
        aym[g] = pack2(-2.0f * ay0, -2.0f * ay1);
        azm[g] = pack2(-2.0f * az0, -2.0f * az1);
    }

    float m[TA];
#pragma unroll
    for (int k = 0; k < TA; ++k) m[k] = 3.402823466e+38f;

    __syncthreads();

    // Software-pipelined hot loop: prefetch j+1's B data (2 LDS.128) before
    // computing on j's, so the 29-cyc LDS latency is covered by ~24 cyc of
    // FFMA2 work + the next iteration's slack. Per j per warp:
    // 2 LDS.128 + 12 FFMA2 (fma pipe, 24 cyc binding) + 8 FMNMX (alu pipe).
    ulonglong2 u0 = smu[0];
    ulonglong2 u1 = smu[1];
#pragma unroll 8
    for (int j = 0; j < BCHUNK; ++j) {
        ulonglong2 p0 = smu[2 * j + 2];
        ulonglong2 p1 = smu[2 * j + 3];
#pragma unroll
        for (int g = 0; g < TA / 2; ++g) {
            unsigned long long t = fma2(axm[g], u0.x, u1.y);   // b2 - 2ax*bx
            t = fma2(aym[g], u0.y, t);
            t = fma2(azm[g], u1.x, t);
            float lo, hi;
            unpack2(t, lo, hi);
            m[2 * g + 0] = fminf(m[2 * g + 0], lo);
            m[2 * g + 1] = fminf(m[2 * g + 1], hi);
        }
        u0 = p0;
        u1 = p1;
    }

    const int slot = (dir * BATCH + b) * NCHUNK + chunk;
    float* pp = g_partial + (size_t)slot * NPTS + tileA * ATILE;
#pragma unroll
    for (int k = 0; k < TA; ++k)
        pp[tid + k * THREADS] = m[k];
}

// ---------------------------------------------------------------------------
// Combine: min over chunks, add a2, clamp at 0, deterministic block-tree sum.
// grid: (NRBLK, BATCH, 2)   block: 256 threads
// ---------------------------------------------------------------------------
__global__ __launch_bounds__(THREADS)
void chamfer_combine(const float* __restrict__ gts, const float* __restrict__ preds) {
    const int dir  = blockIdx.z;
    const int b    = blockIdx.y;
    const int aidx = blockIdx.x * THREADS + threadIdx.x;
    const float* Ab = (dir == 0 ? gts : preds) + (size_t)b * NPTS * 3;

    const int slotbase = (dir * BATCH + b) * NCHUNK;
    float mmin = 3.402823466e+38f;
#pragma unroll
    for (int c = 0; c < NCHUNK; ++c)
        mmin = fminf(mmin, g_partial[(size_t)(slotbase + c) * NPTS + aidx]);

    float ax = Ab[3 * aidx + 0];
    float ay = Ab[3 * aidx + 1];
    float az = Ab[3 * aidx + 2];
    float a2 = ax * ax + ay * ay + az * az;
    float v  = fmaxf(a2 + mmin, 0.0f);   // clamp commutes with min (monotone)

    __shared__ float red[THREADS];
    red[threadIdx.x] = v;
    __syncthreads();
#pragma unroll
    for (int s = THREADS / 2; s > 0; s >>= 1) {
        if (threadIdx.x < s) red[threadIdx.x] += red[threadIdx.x + s];
        __syncthreads();
    }
    if (threadIdx.x == 0)
        g_blocksums[(dir * BATCH + b) * NRBLK + blockIdx.x] = red[0];
}

// ---------------------------------------------------------------------------
// Final: sum the 512 block sums, divide by BATCH*NPTS (both means share the
// denominator since N == M). One block of 512 threads.
// ---------------------------------------------------------------------------
__global__ void chamfer_final(float* __restrict__ out) {
    __shared__ float red[512];
    red[threadIdx.x] = g_blocksums[threadIdx.x];
    __syncthreads();
#pragma unroll
    for (int s = 256; s > 0; s >>= 1) {
        if (threadIdx.x < s) red[threadIdx.x] += red[threadIdx.x + s];
        __syncthreads();
    }
    if (threadIdx.x == 0)
        out[0] = red[0] / (float)(BATCH * NPTS);
}

extern "C" void kernel_launch(void* const* d_in, const int* in_sizes, int n_in,
                              void* d_out, int out_size) {
    const float* gts   = (const float*)d_in[0];
    const float* preds = (const float*)d_in[1];
    (void)in_sizes; (void)n_in; (void)out_size;

    dim3 g1(NATILE * NCHUNK, BATCH, 2);     // 64 x 8 x 2 = 1024 blocks
    chamfer_main<<<g1, THREADS>>>(gts, preds);

    dim3 g2(NRBLK, BATCH, 2);               // 32 x 8 x 2 = 512 blocks
    chamfer_combine<<<g2, THREADS>>>(gts, preds);

    chamfer_final<<<1, 512>>>((float*)d_out);
}

// round 8
// speedup vs baseline: 1.2591x; 1.0365x over previous
#include <cuda_runtime.h>

// ChamferLoss: B=8, N=M=8192, D=3 fp32.
// out = mean_n min_m ||gt_n - pred_m||^2  +  mean_m min_n ||pred_m - gt_n||^2
//
// R7 finding: limiter is RF read-port (even/odd bank) saturation. FFMA2 with
// 3 distinct 64-bit operands costs 3 port-cycles; audit gave 46 port-cyc per
// 256 pairs -> predicted issue 48% / fma 52% / alu 35%, matching ncu exactly.
//
// R7 change: coordinate-major ordering of the FFMA2s so 4 consecutive FFMA2
// share the same B operand register (and group 1 also shares the b2 addend),
// enabling .reuse operand-cache hits -> ~30 port-cyc per 256 pairs.

#define BATCH   8
#define NPTS    8192
#define THREADS 256
#define TA      8                       // A points per thread
#define ATILE   (THREADS * TA)          // 2048 A points per block
#define NATILE  (NPTS / ATILE)          // 4
#define BCHUNK  512                     // B points per block
#define NCHUNK  (NPTS / BCHUNK)         // 16
#define NRBLK   (NPTS / THREADS)        // 32 combine blocks per (b,dir)

__device__ float g_partial[2 * BATCH * NCHUNK * NPTS];   // 8 MB scratch
__device__ float g_blocksums[2 * BATCH * NRBLK];         // 512 floats

__device__ __forceinline__ unsigned long long pack2(float lo, float hi) {
    unsigned long long r;
    asm("mov.b64 %0, {%1, %2};" : "=l"(r) : "f"(lo), "f"(hi));
    return r;
}
__device__ __forceinline__ void unpack2(unsigned long long v, float& lo, float& hi) {
    asm("mov.b64 {%0, %1}, %2;" : "=f"(lo), "=f"(hi) : "l"(v));
}
__device__ __forceinline__ unsigned long long fma2(unsigned long long a,
                                                   unsigned long long b,
                                                   unsigned long long c) {
    unsigned long long d;
    asm("fma.rn.f32x2 %0, %1, %2, %3;" : "=l"(d) : "l"(a), "l"(b), "l"(c));
    return d;
}

// ---------------------------------------------------------------------------
// Main kernel. grid: (NATILE*NCHUNK, BATCH, 2)  block: 256
// ---------------------------------------------------------------------------
__global__ __launch_bounds__(THREADS, 4)
void chamfer_main(const float* __restrict__ gts, const float* __restrict__ preds) {
    const int dir   = blockIdx.z;
    const int b     = blockIdx.y;
    const int tileA = blockIdx.x >> 4;            // / NCHUNK
    const int chunk = blockIdx.x & (NCHUNK - 1);

    const float* Ab = (dir == 0 ? gts : preds) + (size_t)b * NPTS * 3;
    const float* Bb = (dir == 0 ? preds : gts) + (size_t)b * NPTS * 3
                      + (size_t)chunk * BCHUNK * 3;

    // B chunk pre-duplicated into packed f32x2 lanes:
    //   smu[2j]   = { {bx,bx}, {by,by} } ; smu[2j+1] = { {bz,bz}, {b2,b2} }
    __shared__ ulonglong2 smu[2 * BCHUNK + 2];    // ~16 KB (+pad for prefetch)

    const int tid = threadIdx.x;
    for (int i = tid; i < BCHUNK; i += THREADS) {
        float bx = Bb[3 * i + 0];
        float by = Bb[3 * i + 1];
        float bz = Bb[3 * i + 2];
        float b2 = bx * bx + by * by + bz * bz;
        ulonglong2 v0; v0.x = pack2(bx, bx); v0.y = pack2(by, by);
        ulonglong2 v1; v1.x = pack2(bz, bz); v1.y = pack2(b2, b2);
        smu[2 * i + 0] = v0;
        smu[2 * i + 1] = v1;
    }
    if (tid == 0) {
        smu[2 * BCHUNK + 0] = smu[0];
        smu[2 * BCHUNK + 1] = smu[1];
    }

    // A coefficients scaled by -2, packed 2-A-per-f32x2.
    unsigned long long axm[TA / 2], aym[TA / 2], azm[TA / 2];
#pragma unroll
    for (int g = 0; g < TA / 2; ++g) {
        int i0 = tileA * ATILE + tid + (2 * g) * THREADS;
        int i1 = i0 + THREADS;
        float ax0 = Ab[3 * i0 + 0], ay0 = Ab[3 * i0 + 1], az0 = Ab[3 * i0 + 2];
        float ax1 = Ab[3 * i1 + 0], ay1 = Ab[3 * i1 + 1], az1 = Ab[3 * i1 + 2];
        axm[g] = pack2(-2.0f * ax0, -2.0f * ax1);
        aym[g] = pack2(-2.0f * ay0, -2.0f * ay1);
        azm[g] = pack2(-2.0f * az0, -2.0f * az1);
    }

    float m[TA];
#pragma unroll
    for (int k = 0; k < TA; ++k) m[k] = 3.402823466e+38f;

    __syncthreads();

    // Coordinate-major hot loop. Within each coordinate group the 4 FFMA2s
    // carry the SAME B register in the same operand slot (group 1 also the
    // same b2 addend) -> .reuse eliminates most bank reads. Distance-1
    // prefetch of the next B point retained.
    ulonglong2 u0 = smu[0];
    ulonglong2 u1 = smu[1];
#pragma unroll 8
    for (int j = 0; j < BCHUNK; ++j) {
        ulonglong2 p0 = smu[2 * j + 2];
        ulonglong2 p1 = smu[2 * j + 3];

        unsigned long long t[TA / 2];
#pragma unroll
        for (int g = 0; g < TA / 2; ++g)   // slot-b = u0.x, slot-c = u1.y (b2)
            t[g] = fma2(axm[g], u0.x, u1.y);
#pragma unroll
        for (int g = 0; g < TA / 2; ++g)   // slot-b = u0.y shared
            t[g] = fma2(aym[g], u0.y, t[g]);
#pragma unroll
        for (int g = 0; g < TA / 2; ++g)   // slot-b = u1.x shared
            t[g] = fma2(azm[g], u1.x, t[g]);
#pragma unroll
        for (int g = 0; g < TA / 2; ++g) {
            float lo, hi;
            unpack2(t[g], lo, hi);
            m[2 * g + 0] = fminf(m[2 * g + 0], lo);
            m[2 * g + 1] = fminf(m[2 * g + 1], hi);
        }
        u0 = p0;
        u1 = p1;
    }

    const int slot = (dir * BATCH + b) * NCHUNK + chunk;
    float* pp = g_partial + (size_t)slot * NPTS + tileA * ATILE;
#pragma unroll
    for (int k = 0; k < TA; ++k)
        pp[tid + k * THREADS] = m[k];
}

// ---------------------------------------------------------------------------
// Combine: min over chunks, add a2, clamp, deterministic block-tree sum.
// ---------------------------------------------------------------------------
__global__ __launch_bounds__(THREADS)
void chamfer_combine(const float* __restrict__ gts, const float* __restrict__ preds) {
    const int dir  = blockIdx.z;
    const int b    = blockIdx.y;
    const int aidx = blockIdx.x * THREADS + threadIdx.x;
    const float* Ab = (dir == 0 ? gts : preds) + (size_t)b * NPTS * 3;

    const int slotbase = (dir * BATCH + b) * NCHUNK;
    float mmin = 3.402823466e+38f;
#pragma unroll
    for (int c = 0; c < NCHUNK; ++c)
        mmin = fminf(mmin, g_partial[(size_t)(slotbase + c) * NPTS + aidx]);

    float ax = Ab[3 * aidx + 0];
    float ay = Ab[3 * aidx + 1];
    float az = Ab[3 * aidx + 2];
    float a2 = ax * ax + ay * ay + az * az;
    float v  = fmaxf(a2 + mmin, 0.0f);

    __shared__ float red[THREADS];
    red[threadIdx.x] = v;
    __syncthreads();
#pragma unroll
    for (int s = THREADS / 2; s > 0; s >>= 1) {
        if (threadIdx.x < s) red[threadIdx.x] += red[threadIdx.x + s];
        __syncthreads();
    }
    if (threadIdx.x == 0)
        g_blocksums[(dir * BATCH + b) * NRBLK + blockIdx.x] = red[0];
}

__global__ void chamfer_final(float* __restrict__ out) {
    __shared__ float red[512];
    red[threadIdx.x] = g_blocksums[threadIdx.x];
    __syncthreads();
#pragma unroll
    for (int s = 256; s > 0; s >>= 1) {
        if (threadIdx.x < s) red[threadIdx.x] += red[threadIdx.x + s];
        __syncthreads();
    }
    if (threadIdx.x == 0)
        out[0] = red[0] / (float)(BATCH * NPTS);
}

extern "C" void kernel_launch(void* const* d_in, const int* in_sizes, int n_in,
                              void* d_out, int out_size) {
    const float* gts   = (const float*)d_in[0];
    const float* preds = (const float*)d_in[1];
    (void)in_sizes; (void)n_in; (void)out_size;

    dim3 g1(NATILE * NCHUNK, BATCH, 2);
    chamfer_main<<<g1, THREADS>>>(gts, preds);

    dim3 g2(NRBLK, BATCH, 2);
    chamfer_combine<<<g2, THREADS>>>(gts, preds);

    chamfer_final<<<1, 512>>>((float*)d_out);
}